// round 11
// baseline (speedup 1.0000x reference)
#include <cuda_runtime.h>

typedef unsigned long long u64;

// Pre-duplicated twiddles: scalar i of twiddle tensor -> float2 (v, v).
// Layout: scalar index i = (stage*512 + pair)*4 + e, e in {t00,t01,t10,t11}.
// As ulonglong2: entry (stage*512+pair)*2   = (m0m0, m1m1)
//                entry (stage*512+pair)*2+1 = (m2m2, m3m3)
__device__ ulonglong2 g_twdup[10240];   // 160KB
__device__ float2     g_bdup[1024];     // bias duplicated

__global__ void twprep_kernel(const float* __restrict__ tw,
                              const float* __restrict__ bias){
  int i = blockIdx.x * 256 + threadIdx.x;   // 0..21503
  if (i < 20480){
    float v = tw[i];
    ((float2*)g_twdup)[i] = make_float2(v, v);
  } else {
    int b = i - 20480;
    float v = bias[b];
    g_bdup[b] = make_float2(v, v);
  }
}

__device__ __forceinline__ void upk2(u64 v, float& lo, float& hi){
  asm("mov.b64 {%0,%1}, %2;" : "=f"(lo), "=f"(hi) : "l"(v));
}
__device__ __forceinline__ u64 fma2(u64 a, u64 b, u64 c){
  u64 d; asm("fma.rn.f32x2 %0, %1, %2, %3;" : "=l"(d) : "l"(a), "l"(b), "l"(c)); return d;
}
__device__ __forceinline__ u64 mul2(u64 a, u64 b){
  u64 d; asm("mul.rn.f32x2 %0, %1, %2;" : "=l"(d) : "l"(a), "l"(b)); return d;
}
__device__ __forceinline__ u64 add2(u64 a, u64 b){
  u64 d; asm("add.rn.f32x2 %0, %1, %2;" : "=l"(d) : "l"(a), "l"(b)); return d;
}
__device__ __forceinline__ u64 pk2(float lo, float hi){
  u64 r; asm volatile("mov.b64 %0, {%1,%2};" : "=l"(r) : "f"(lo), "f"(hi)); return r;
}

// 16 rows per CTA stored as 4 quads of 4 rows; one 16B slot per (position, quad).
// slot = (quad ^ (p>>1) ^ (p>>3)) & 3. (R5 layout — address math stays uniform.)
__device__ __forceinline__ int widx(int pos, int quad){
  return (pos << 4) + (((quad ^ (pos >> 1) ^ (pos >> 3)) & 3) << 2);
}

// Butterfly on one pair of positions for 4 rows, twiddles pre-duplicated:
// A = (m0,m1), B = (m2,m3) as packed f32x2 lanes. No packing MOVs.
__device__ __forceinline__ void bflyq2(u64& x0a, u64& x0b, u64& x1a, u64& x1b,
                                       ulonglong2 A, ulonglong2 B){
  u64 a = x0a, b = x1a;
  x0a = fma2(A.x, a, mul2(A.y, b));
  x1a = fma2(B.x, a, mul2(B.y, b));
  a = x0b; b = x1b;
  x0b = fma2(A.x, a, mul2(A.y, b));
  x1b = fma2(B.x, a, mul2(B.y, b));
}

// Butterfly on one pair of positions for 2 rows (one packed f32x2 lane).
__device__ __forceinline__ void bfly12(u64& x0, u64& x1,
                                       ulonglong2 A, ulonglong2 B){
  u64 a = x0, b = x1;
  x0 = fma2(A.x, a, mul2(A.y, b));
  x1 = fma2(B.x, a, mul2(B.y, b));
}

__global__ __launch_bounds__(256, 2)
void butterfly_kernel(const float* __restrict__ x,
                      float* __restrict__ out)
{
  extern __shared__ float sdata[];   // 1024 pos * 16 rows * 4B = 64KB
  const ulonglong2* __restrict__ td = g_twdup;
  const int tid = threadIdx.x;
  const int o   = tid & 127;         // position-octet index (P1/P2)
  const int sub = tid >> 7;          // which 8 of the 16 rows (P1/P2)
  const long long rowbase = (long long)blockIdx.x * 16 + sub * 8;

  // ================= PASS 1: stages 0-2 (stride 1,2,4), global -> smem ======
  #pragma unroll
  for (int g = 0; g < 2; g++){
    const int quad = 2 * sub + g;    // quad q holds rows blk*16 + 4q + {0..3}
    const float* base = x + (rowbase + 4 * g) * 1024 + 8 * o;
    float4 a0 = *(const float4*)(base        );
    float4 b0 = *(const float4*)(base +    4 );
    float4 a1 = *(const float4*)(base + 1024 );
    float4 b1 = *(const float4*)(base + 1028 );
    float4 a2 = *(const float4*)(base + 2048 );
    float4 b2 = *(const float4*)(base + 2052 );
    float4 a3 = *(const float4*)(base + 3072 );
    float4 b3 = *(const float4*)(base + 3076 );
    u64 v01[8], v23[8];
    v01[0]=pk2(a0.x,a1.x); v01[1]=pk2(a0.y,a1.y); v01[2]=pk2(a0.z,a1.z); v01[3]=pk2(a0.w,a1.w);
    v01[4]=pk2(b0.x,b1.x); v01[5]=pk2(b0.y,b1.y); v01[6]=pk2(b0.z,b1.z); v01[7]=pk2(b0.w,b1.w);
    v23[0]=pk2(a2.x,a3.x); v23[1]=pk2(a2.y,a3.y); v23[2]=pk2(a2.z,a3.z); v23[3]=pk2(a2.w,a3.w);
    v23[4]=pk2(b2.x,b3.x); v23[5]=pk2(b2.y,b3.y); v23[6]=pk2(b2.z,b3.z); v23[7]=pk2(b2.w,b3.w);

    // stage 0: pairs (2i, 2i+1), tw pair 4o+i
    #pragma unroll
    for (int i = 0; i < 4; i++){
      const int t2 = (0 * 512 + 4 * o + i) * 2;
      bflyq2(v01[2*i], v23[2*i], v01[2*i+1], v23[2*i+1], td[t2], td[t2+1]);
    }
    // stage 1: pairs (0,2)(1,3)(4,6)(5,7), tw pair 4o+i
    #pragma unroll
    for (int i = 0; i < 4; i++){
      const int a = (i & 1) + 4 * (i >> 1);
      const int t2 = (1 * 512 + 4 * o + i) * 2;
      bflyq2(v01[a], v23[a], v01[a+2], v23[a+2], td[t2], td[t2+1]);
    }
    // stage 2: pairs (i, i+4), tw pair 4o+i
    #pragma unroll
    for (int i = 0; i < 4; i++){
      const int t2 = (2 * 512 + 4 * o + i) * 2;
      bflyq2(v01[i], v23[i], v01[i+4], v23[i+4], td[t2], td[t2+1]);
    }

    #pragma unroll
    for (int c = 0; c < 8; c++){
      ulonglong2 u; u.x = v01[c]; u.y = v23[c];
      *(ulonglong2*)&sdata[widx(8 * o + c, quad)] = u;
    }
  }
  __syncthreads();

  // ================= PASS 2: stages 3-5 (stride 8,16,32) ====================
  {
    const int bb = o >> 3, j = o & 7;
    #pragma unroll
    for (int g = 0; g < 2; g++){
      const int quad = 2 * sub + g;
      u64 v01[8], v23[8];
      #pragma unroll
      for (int k = 0; k < 8; k++){
        ulonglong2 u = *(ulonglong2*)&sdata[widx(64 * bb + 8 * k + j, quad)];
        v01[k] = u.x; v23[k] = u.y;
      }
      // stage 3: pairs (2i, 2i+1), tw pair 32bb + j + 8i
      #pragma unroll
      for (int i = 0; i < 4; i++){
        const int t2 = (3 * 512 + 32 * bb + j + 8 * i) * 2;
        bflyq2(v01[2*i], v23[2*i], v01[2*i+1], v23[2*i+1], td[t2], td[t2+1]);
      }
      // stage 4: pairs (0,2)(1,3)(4,6)(5,7)
      #pragma unroll
      for (int i = 0; i < 4; i++){
        const int a = (i & 1) + 4 * (i >> 1);
        const int t2 = (4 * 512 + 32 * bb + j + 8 * i) * 2;
        bflyq2(v01[a], v23[a], v01[a+2], v23[a+2], td[t2], td[t2+1]);
      }
      // stage 5: pairs (i, i+4)
      #pragma unroll
      for (int i = 0; i < 4; i++){
        const int t2 = (5 * 512 + 32 * bb + j + 8 * i) * 2;
        bflyq2(v01[i], v23[i], v01[i+4], v23[i+4], td[t2], td[t2+1]);
      }
      #pragma unroll
      for (int k = 0; k < 8; k++){
        ulonglong2 u; u.x = v01[k]; u.y = v23[k];
        *(ulonglong2*)&sdata[widx(64 * bb + 8 * k + j, quad)] = u;
      }
    }
  }
  __syncthreads();

  // ====== PASS 3: stages 6-9 (stride 64,128,256,512) + bias -> global =======
  // Thread owns pos = j2 + 64m, m=0..15, for one quad (4 rows).
  {
    const int j2 = tid & 63;
    const int q  = tid >> 6;
    u64 v01[16], v23[16];
    #pragma unroll
    for (int m = 0; m < 16; m++){
      ulonglong2 u = *(ulonglong2*)&sdata[widx(j2 + 64 * m, q)];
      v01[m] = u.x; v23[m] = u.y;
    }
    // stage 6 (S=64): pairs (2r, 2r+1); tw pair 64r + j2
    #pragma unroll
    for (int r = 0; r < 8; r++){
      const int t2 = (6 * 512 + 64 * r + j2) * 2;
      ulonglong2 A = td[t2], B = td[t2+1];
      bfly12(v01[2*r], v01[2*r+1], A, B);
      bfly12(v23[2*r], v23[2*r+1], A, B);
    }
    // stage 7 (S=128): pairs (4r+h, 4r+h+2); tw pair 128r + 64h + j2
    #pragma unroll
    for (int r = 0; r < 4; r++){
      #pragma unroll
      for (int h = 0; h < 2; h++){
        const int t2 = (7 * 512 + 128 * r + 64 * h + j2) * 2;
        ulonglong2 A = td[t2], B = td[t2+1];
        const int m0 = 4 * r + h;
        bfly12(v01[m0], v01[m0+2], A, B);
        bfly12(v23[m0], v23[m0+2], A, B);
      }
    }
    // stage 8 (S=256): pairs (8r+h, 8r+h+4); tw pair 256r + 64h + j2
    #pragma unroll
    for (int r = 0; r < 2; r++){
      #pragma unroll
      for (int h = 0; h < 4; h++){
        const int t2 = (8 * 512 + 256 * r + 64 * h + j2) * 2;
        ulonglong2 A = td[t2], B = td[t2+1];
        const int m0 = 8 * r + h;
        bfly12(v01[m0], v01[m0+4], A, B);
        bfly12(v23[m0], v23[m0+4], A, B);
      }
    }
    // stage 9 (S=512): pairs (h, h+8); tw pair 64h + j2
    #pragma unroll
    for (int h = 0; h < 8; h++){
      const int t2 = (9 * 512 + 64 * h + j2) * 2;
      ulonglong2 A = td[t2], B = td[t2+1];
      bfly12(v01[h], v01[h+8], A, B);
      bfly12(v23[h], v23[h+8], A, B);
    }
    // bias (pre-duplicated) + store (lanes j2 consecutive -> coalesced STG.32)
    const long long r0 = (long long)blockIdx.x * 16 + 4 * q;
    float* obase = out + r0 * 1024 + j2;
    #pragma unroll
    for (int m = 0; m < 16; m++){
      u64 b2 = *(const u64*)&g_bdup[j2 + 64 * m];
      u64 ylo = add2(v01[m], b2);
      u64 yhi = add2(v23[m], b2);
      float f0, f1, f2, f3;
      upk2(ylo, f0, f1); upk2(yhi, f2, f3);
      float* op = obase + 64 * m;
      op[0]    = f0;
      op[1024] = f1;
      op[2048] = f2;
      op[3072] = f3;
    }
  }
}

extern "C" void kernel_launch(void* const* d_in, const int* in_sizes, int n_in,
                              void* d_out, int out_size)
{
  const float* x    = (const float*)d_in[0];   // (32768, 1024) f32
  const float* tw   = (const float*)d_in[1];   // (1, 10, 512, 2, 2) f32
  const float* bias = (const float*)d_in[2];   // (1024,) f32
  float* out = (float*)d_out;                  // (32768, 1024) f32

  const int batch = in_sizes[0] / 1024;
  const int smem_bytes = 1024 * 16 * 4;        // 64KB data tile

  // Prep: duplicate twiddles+bias into f32x2-lane format (21504 items).
  twprep_kernel<<<84, 256>>>(tw, bias);

  cudaFuncSetAttribute(butterfly_kernel,
                       cudaFuncAttributeMaxDynamicSharedMemorySize, smem_bytes);
  butterfly_kernel<<<batch / 16, 256, smem_bytes>>>(x, out);
}

// round 12
// speedup vs baseline: 3.2189x; 3.2189x over previous
#include <cuda_runtime.h>

typedef unsigned long long u64;

__device__ __forceinline__ u64 pk2(float lo, float hi){
  u64 r; asm volatile("mov.b64 %0, {%1,%2};" : "=l"(r) : "f"(lo), "f"(hi)); return r;
}
__device__ __forceinline__ void upk2(u64 v, float& lo, float& hi){
  asm("mov.b64 {%0,%1}, %2;" : "=f"(lo), "=f"(hi) : "l"(v));
}
__device__ __forceinline__ u64 fma2(u64 a, u64 b, u64 c){
  u64 d; asm("fma.rn.f32x2 %0, %1, %2, %3;" : "=l"(d) : "l"(a), "l"(b), "l"(c)); return d;
}
__device__ __forceinline__ u64 mul2(u64 a, u64 b){
  u64 d; asm("mul.rn.f32x2 %0, %1, %2;" : "=l"(d) : "l"(a), "l"(b)); return d;
}
__device__ __forceinline__ u64 add2(u64 a, u64 b){
  u64 d; asm("add.rn.f32x2 %0, %1, %2;" : "=l"(d) : "l"(a), "l"(b)); return d;
}

// Half-CTA barrier: half h (0/1) syncs its own 128 threads (4 warps).
__device__ __forceinline__ void half_bar(int h){
  asm volatile("bar.sync %0, 128;" :: "r"(h + 1) : "memory");
}

// 16 rows per CTA stored as 4 quads of 4 rows; one 16B slot per (position, quad).
// slot = (quad ^ (p>>1) ^ (p>>3)) & 3. (R5 layout — address math stays uniform.)
__device__ __forceinline__ int widx(int pos, int quad){
  return (pos << 4) + (((quad ^ (pos >> 1) ^ (pos >> 3)) & 3) << 2);
}

// Butterfly on one pair of positions for 4 rows (2 packed f32x2 lanes each).
__device__ __forceinline__ void bflyq(u64& x0a, u64& x0b, u64& x1a, u64& x1b,
                                      const float* t){
  u64 m0 = pk2(t[0], t[0]);
  u64 m1 = pk2(t[1], t[1]);
  u64 m2 = pk2(t[2], t[2]);
  u64 m3 = pk2(t[3], t[3]);
  u64 a = x0a, b = x1a;
  x0a = fma2(m0, a, mul2(m1, b));
  x1a = fma2(m2, a, mul2(m3, b));
  a = x0b; b = x1b;
  x0b = fma2(m0, a, mul2(m1, b));
  x1b = fma2(m2, a, mul2(m3, b));
}

// 3 stages on 8 local elements (local strides 1,2,4).
__device__ __forceinline__ void radix8q(u64 v01[8], u64 v23[8], const float tw[48]){
  bflyq(v01[0],v23[0], v01[1],v23[1], tw+ 0);
  bflyq(v01[2],v23[2], v01[3],v23[3], tw+ 4);
  bflyq(v01[4],v23[4], v01[5],v23[5], tw+ 8);
  bflyq(v01[6],v23[6], v01[7],v23[7], tw+12);
  bflyq(v01[0],v23[0], v01[2],v23[2], tw+16);
  bflyq(v01[1],v23[1], v01[3],v23[3], tw+20);
  bflyq(v01[4],v23[4], v01[6],v23[6], tw+24);
  bflyq(v01[5],v23[5], v01[7],v23[7], tw+28);
  bflyq(v01[0],v23[0], v01[4],v23[4], tw+32);
  bflyq(v01[1],v23[1], v01[5],v23[5], tw+36);
  bflyq(v01[2],v23[2], v01[6],v23[6], tw+40);
  bflyq(v01[3],v23[3], v01[7],v23[7], tw+44);
}

__device__ __forceinline__ void load_tw(const float4* __restrict__ tw4,
                                        int s0, int pbase, int pstride, float tw[48]){
  #pragma unroll
  for (int s = 0; s < 3; s++){
    #pragma unroll
    for (int i = 0; i < 4; i++){
      float4 t = tw4[(s0 + s) * 512 + pbase + i * pstride];
      tw[(s*4+i)*4+0] = t.x; tw[(s*4+i)*4+1] = t.y;
      tw[(s*4+i)*4+2] = t.z; tw[(s*4+i)*4+3] = t.w;
    }
  }
}

// Data tile: 16384 floats (64KB).
// Padded stage0-2 twiddle stash: float4 p of stage s lives at float offset
// TWF + s*2560 + 4p + 4*(p>>2) (consumer reads at 20o + immediates,
// conflict-free LDS.128).
#define TWF 16384
#define TWS 2560

__global__ __launch_bounds__(256, 2)
void butterfly_kernel(const float* __restrict__ x,
                      const float* __restrict__ twg,
                      const float* __restrict__ bias,
                      float* __restrict__ out)
{
  extern __shared__ float sdata[];   // 64KB data tile + 30KB padded tw stash
  const float4* tw4 = (const float4*)twg;
  const int tid = threadIdx.x;
  const int o   = tid & 127;         // position-octet index (P1/P2)
  const int sub = tid >> 7;          // row-half: 0 -> rows 0-7, 1 -> rows 8-15
  const long long rowbase = (long long)blockIdx.x * 16 + sub * 8;

  // ---- Hoist g=0 x-loads above the stash fill + barrier (hide DRAM lat) ----
  const float* base0 = x + rowbase * 1024 + 8 * o;
  float4 a0 = *(const float4*)(base0        );
  float4 b0 = *(const float4*)(base0 +    4 );
  float4 a1 = *(const float4*)(base0 + 1024 );
  float4 b1 = *(const float4*)(base0 + 1028 );
  float4 a2 = *(const float4*)(base0 + 2048 );
  float4 b2 = *(const float4*)(base0 + 2052 );
  float4 a3 = *(const float4*)(base0 + 3072 );
  float4 b3 = *(const float4*)(base0 + 3076 );

  // ---- Stage the stage-0..2 twiddles coalesced into the padded stash ----
  #pragma unroll
  for (int i = 0; i < 6; i++){
    int p  = tid + 256 * i;
    float4 t = tw4[p];
    int s  = p >> 9;
    int pp = p & 511;
    *(float4*)&sdata[TWF + s * TWS + 4 * pp + 4 * (pp >> 2)] = t;
  }
  __syncthreads();   // stash is written by all 256 threads -> full barrier

  float tw[48];

  // ================= PASS 1: stages 0-2 (stride 1,2,4), global -> smem ======
  // Twiddles from the padded stash: float offset TWF + s*TWS + 20o + 4q.
  {
    const float* tb = &sdata[TWF + 20 * o];
    #pragma unroll
    for (int s = 0; s < 3; s++){
      #pragma unroll
      for (int qq = 0; qq < 4; qq++){
        float4 t = *(const float4*)&tb[s * TWS + 4 * qq];
        tw[(s*4+qq)*4+0] = t.x; tw[(s*4+qq)*4+1] = t.y;
        tw[(s*4+qq)*4+2] = t.z; tw[(s*4+qq)*4+3] = t.w;
      }
    }
  }
  // ---- g = 0 (x already in registers) ----
  {
    const int quad = 2 * sub;
    u64 v01[8], v23[8];
    v01[0]=pk2(a0.x,a1.x); v01[1]=pk2(a0.y,a1.y); v01[2]=pk2(a0.z,a1.z); v01[3]=pk2(a0.w,a1.w);
    v01[4]=pk2(b0.x,b1.x); v01[5]=pk2(b0.y,b1.y); v01[6]=pk2(b0.z,b1.z); v01[7]=pk2(b0.w,b1.w);
    v23[0]=pk2(a2.x,a3.x); v23[1]=pk2(a2.y,a3.y); v23[2]=pk2(a2.z,a3.z); v23[3]=pk2(a2.w,a3.w);
    v23[4]=pk2(b2.x,b3.x); v23[5]=pk2(b2.y,b3.y); v23[6]=pk2(b2.z,b3.z); v23[7]=pk2(b2.w,b3.w);
    radix8q(v01, v23, tw);
    #pragma unroll
    for (int c = 0; c < 8; c++){
      ulonglong2 u; u.x = v01[c]; u.y = v23[c];
      *(ulonglong2*)&sdata[widx(8 * o + c, quad)] = u;
    }
  }
  // ---- g = 1 ----
  {
    const int quad = 2 * sub + 1;
    const float* base = base0 + 4 * 1024;
    float4 c0 = *(const float4*)(base        );
    float4 d0 = *(const float4*)(base +    4 );
    float4 c1 = *(const float4*)(base + 1024 );
    float4 d1 = *(const float4*)(base + 1028 );
    float4 c2 = *(const float4*)(base + 2048 );
    float4 d2 = *(const float4*)(base + 2052 );
    float4 c3 = *(const float4*)(base + 3072 );
    float4 d3 = *(const float4*)(base + 3076 );
    u64 v01[8], v23[8];
    v01[0]=pk2(c0.x,c1.x); v01[1]=pk2(c0.y,c1.y); v01[2]=pk2(c0.z,c1.z); v01[3]=pk2(c0.w,c1.w);
    v01[4]=pk2(d0.x,d1.x); v01[5]=pk2(d0.y,d1.y); v01[6]=pk2(d0.z,d1.z); v01[7]=pk2(d0.w,d1.w);
    v23[0]=pk2(c2.x,c3.x); v23[1]=pk2(c2.y,c3.y); v23[2]=pk2(c2.z,c3.z); v23[3]=pk2(c2.w,c3.w);
    v23[4]=pk2(d2.x,d3.x); v23[5]=pk2(d2.y,d3.y); v23[6]=pk2(d2.z,d3.z); v23[7]=pk2(d2.w,d3.w);
    radix8q(v01, v23, tw);
    #pragma unroll
    for (int c = 0; c < 8; c++){
      ulonglong2 u; u.x = v01[c]; u.y = v23[c];
      *(ulonglong2*)&sdata[widx(8 * o + c, quad)] = u;
    }
  }

  // Hoist P2 twiddle loads above the barrier (independent of the data tile).
  const int bb = o >> 3, j = o & 7;
  load_tw(tw4, 3, 32 * bb + j, 8, tw);

  // The data tile is half-private (quads 2sub, 2sub+1 <-> tids of this half):
  // sync only within the half.
  half_bar(sub);

  // ================= PASS 2: stages 3-5 (stride 8,16,32) ====================
  {
    #pragma unroll
    for (int g = 0; g < 2; g++){
      const int quad = 2 * sub + g;
      u64 v01[8], v23[8];
      #pragma unroll
      for (int k = 0; k < 8; k++){
        ulonglong2 u = *(ulonglong2*)&sdata[widx(64 * bb + 8 * k + j, quad)];
        v01[k] = u.x; v23[k] = u.y;
      }
      radix8q(v01, v23, tw);
      #pragma unroll
      for (int k = 0; k < 8; k++){
        ulonglong2 u; u.x = v01[k]; u.y = v23[k];
        *(ulonglong2*)&sdata[widx(64 * bb + 8 * k + j, quad)] = u;
      }
    }
  }

  // Hoist bias loads above the barrier (independent of the data tile).
  const int j2 = tid & 63;
  const int q  = tid >> 6;           // quad 0..3; q>>1 == sub for this thread
  float bs[16];
  #pragma unroll
  for (int m = 0; m < 16; m++) bs[m] = bias[j2 + 64 * m];

  half_bar(sub);

  // ====== PASS 3: stages 6-9 (stride 64,128,256,512) + bias -> global =======
  // Thread owns pos = j2 + 64m, m=0..15, for one quad (4 rows); quads 2sub
  // and 2sub+1 were produced by this half. All four stages in registers.
  {
    u64 v01[16], v23[16];
    #pragma unroll
    for (int m = 0; m < 16; m++){
      ulonglong2 u = *(ulonglong2*)&sdata[widx(j2 + 64 * m, q)];
      v01[m] = u.x; v23[m] = u.y;
    }
    // stage 6 (S=64): pairs (2r, 2r+1); tw idx = 64r + j2
    #pragma unroll
    for (int r = 0; r < 8; r++){
      float4 t = tw4[6 * 512 + 64 * r + j2];
      float tm[4] = {t.x, t.y, t.z, t.w};
      bflyq(v01[2*r], v23[2*r], v01[2*r+1], v23[2*r+1], tm);
    }
    // stage 7 (S=128): pairs (4r+h, 4r+h+2); tw idx = 128r + 64h + j2
    #pragma unroll
    for (int r = 0; r < 4; r++){
      #pragma unroll
      for (int h = 0; h < 2; h++){
        float4 t = tw4[7 * 512 + 128 * r + 64 * h + j2];
        float tm[4] = {t.x, t.y, t.z, t.w};
        const int m0 = 4 * r + h;
        bflyq(v01[m0], v23[m0], v01[m0+2], v23[m0+2], tm);
      }
    }
    // stage 8 (S=256): pairs (8r+h, 8r+h+4); tw idx = 256r + 64h + j2
    #pragma unroll
    for (int r = 0; r < 2; r++){
      #pragma unroll
      for (int h = 0; h < 4; h++){
        float4 t = tw4[8 * 512 + 256 * r + 64 * h + j2];
        float tm[4] = {t.x, t.y, t.z, t.w};
        const int m0 = 8 * r + h;
        bflyq(v01[m0], v23[m0], v01[m0+4], v23[m0+4], tm);
      }
    }
    // stage 9 (S=512): pairs (h, h+8); tw idx = 64h + j2
    #pragma unroll
    for (int h = 0; h < 8; h++){
      float4 t = tw4[9 * 512 + 64 * h + j2];
      float tm[4] = {t.x, t.y, t.z, t.w};
      bflyq(v01[h], v23[h], v01[h+8], v23[h+8], tm);
    }
    // bias + store (lanes j2 consecutive -> 128B-coalesced STG.32)
    const long long r0 = (long long)blockIdx.x * 16 + 4 * q;
    float* obase = out + r0 * 1024 + j2;
    #pragma unroll
    for (int m = 0; m < 16; m++){
      u64 b2 = pk2(bs[m], bs[m]);
      u64 ylo = add2(v01[m], b2);
      u64 yhi = add2(v23[m], b2);
      float f0, f1, f2, f3;
      upk2(ylo, f0, f1); upk2(yhi, f2, f3);
      float* op = obase + 64 * m;
      op[0]    = f0;
      op[1024] = f1;
      op[2048] = f2;
      op[3072] = f3;
    }
  }
}

extern "C" void kernel_launch(void* const* d_in, const int* in_sizes, int n_in,
                              void* d_out, int out_size)
{
  const float* x    = (const float*)d_in[0];   // (32768, 1024) f32
  const float* tw   = (const float*)d_in[1];   // (1, 10, 512, 2, 2) f32
  const float* bias = (const float*)d_in[2];   // (1024,) f32
  float* out = (float*)d_out;                  // (32768, 1024) f32

  const int batch = in_sizes[0] / 1024;
  const int smem_bytes = (16384 + 3 * 2560) * 4;   // 64KB data + 30KB tw stash

  cudaFuncSetAttribute(butterfly_kernel,
                       cudaFuncAttributeMaxDynamicSharedMemorySize, smem_bytes);
  butterfly_kernel<<<batch / 16, 256, smem_bytes>>>(x, tw, bias, out);
}

// round 15
// speedup vs baseline: 3.2263x; 1.0023x over previous
#include <cuda_runtime.h>

typedef unsigned long long u64;

__device__ __forceinline__ u64 pk2(float lo, float hi){
  u64 r; asm volatile("mov.b64 %0, {%1,%2};" : "=l"(r) : "f"(lo), "f"(hi)); return r;
}
__device__ __forceinline__ void upk2(u64 v, float& lo, float& hi){
  asm("mov.b64 {%0,%1}, %2;" : "=f"(lo), "=f"(hi) : "l"(v));
}
__device__ __forceinline__ u64 fma2(u64 a, u64 b, u64 c){
  u64 d; asm("fma.rn.f32x2 %0, %1, %2, %3;" : "=l"(d) : "l"(a), "l"(b), "l"(c)); return d;
}
__device__ __forceinline__ u64 mul2(u64 a, u64 b){
  u64 d; asm("mul.rn.f32x2 %0, %1, %2;" : "=l"(d) : "l"(a), "l"(b)); return d;
}
__device__ __forceinline__ u64 add2(u64 a, u64 b){
  u64 d; asm("add.rn.f32x2 %0, %1, %2;" : "=l"(d) : "l"(a), "l"(b)); return d;
}

// Half-CTA barrier: half h (0/1) syncs its own 128 threads (ids 1,2).
__device__ __forceinline__ void half_bar(int h){
  asm volatile("bar.sync %0, 128;" :: "r"(h + 1) : "memory");
}
// Pair-warp barrier: warps {w, w+4} (64 threads) sync on id 4+(w&3).
__device__ __forceinline__ void pair_bar(int wid){
  asm volatile("bar.sync %0, 64;" :: "r"(4 + (wid & 3)) : "memory");
}

// 16 rows per CTA stored as 4 quads of 4 rows; one 16B slot per (position, quad).
// slot = (quad ^ (p>>1) ^ (p>>3)) & 3. (R5 layout — address math stays uniform.)
__device__ __forceinline__ int widx(int pos, int quad){
  return (pos << 4) + (((quad ^ (pos >> 1) ^ (pos >> 3)) & 3) << 2);
}

// Butterfly on one pair of positions for 4 rows (2 packed f32x2 lanes each).
__device__ __forceinline__ void bflyq(u64& x0a, u64& x0b, u64& x1a, u64& x1b,
                                      const float* t){
  u64 m0 = pk2(t[0], t[0]);
  u64 m1 = pk2(t[1], t[1]);
  u64 m2 = pk2(t[2], t[2]);
  u64 m3 = pk2(t[3], t[3]);
  u64 a = x0a, b = x1a;
  x0a = fma2(m0, a, mul2(m1, b));
  x1a = fma2(m2, a, mul2(m3, b));
  a = x0b; b = x1b;
  x0b = fma2(m0, a, mul2(m1, b));
  x1b = fma2(m2, a, mul2(m3, b));
}

// 3 stages on 8 local elements (local strides 1,2,4).
__device__ __forceinline__ void radix8q(u64 v01[8], u64 v23[8], const float tw[48]){
  bflyq(v01[0],v23[0], v01[1],v23[1], tw+ 0);
  bflyq(v01[2],v23[2], v01[3],v23[3], tw+ 4);
  bflyq(v01[4],v23[4], v01[5],v23[5], tw+ 8);
  bflyq(v01[6],v23[6], v01[7],v23[7], tw+12);
  bflyq(v01[0],v23[0], v01[2],v23[2], tw+16);
  bflyq(v01[1],v23[1], v01[3],v23[3], tw+20);
  bflyq(v01[4],v23[4], v01[6],v23[6], tw+24);
  bflyq(v01[5],v23[5], v01[7],v23[7], tw+28);
  bflyq(v01[0],v23[0], v01[4],v23[4], tw+32);
  bflyq(v01[1],v23[1], v01[5],v23[5], tw+36);
  bflyq(v01[2],v23[2], v01[6],v23[6], tw+40);
  bflyq(v01[3],v23[3], v01[7],v23[7], tw+44);
}

__device__ __forceinline__ void load_tw(const float4* __restrict__ tw4,
                                        int s0, int pbase, int pstride, float tw[48]){
  #pragma unroll
  for (int s = 0; s < 3; s++){
    #pragma unroll
    for (int i = 0; i < 4; i++){
      float4 t = tw4[(s0 + s) * 512 + pbase + i * pstride];
      tw[(s*4+i)*4+0] = t.x; tw[(s*4+i)*4+1] = t.y;
      tw[(s*4+i)*4+2] = t.z; tw[(s*4+i)*4+3] = t.w;
    }
  }
}

// Data tile: 16384 floats (64KB).
// Padded stage0-2 twiddle stash: float4 p of stage s lives at float offset
// TWF + s*2560 + 4p + 4*(p>>2) (consumer reads at 20o + immediates,
// conflict-free LDS.128).
#define TWF 16384
#define TWS 2560

__global__ __launch_bounds__(256, 2)
void butterfly_kernel(const float* __restrict__ x,
                      const float* __restrict__ twg,
                      const float* __restrict__ bias,
                      float* __restrict__ out)
{
  extern __shared__ float sdata[];   // 64KB data tile + 30KB padded tw stash
  const float4* tw4 = (const float4*)twg;
  const int tid = threadIdx.x;
  const int wid = tid >> 5;
  const int o   = tid & 127;         // position-octet index (P1/P2)
  const int sub = tid >> 7;          // row-half: 0 -> rows 0-7, 1 -> rows 8-15
  const long long rowbase = (long long)blockIdx.x * 16 + sub * 8;

  // ---- Hoist g=0 x-loads above the stash fill + barrier (hide DRAM lat) ----
  const float* base0 = x + rowbase * 1024 + 8 * o;
  float4 a0 = *(const float4*)(base0        );
  float4 b0 = *(const float4*)(base0 +    4 );
  float4 a1 = *(const float4*)(base0 + 1024 );
  float4 b1 = *(const float4*)(base0 + 1028 );
  float4 a2 = *(const float4*)(base0 + 2048 );
  float4 b2 = *(const float4*)(base0 + 2052 );
  float4 a3 = *(const float4*)(base0 + 3072 );
  float4 b3 = *(const float4*)(base0 + 3076 );

  // ---- Stage stage-0..2 twiddles into the padded stash, PAIR-WARP style ----
  // Warp pair {w, w+4} (w = wid&3) fills the slice its o-range [32w..32w+31]
  // consumes: stage s float4 indices [128w..128w+127]. Intra-pair index
  // t64p = lane + 32*sub spans 0..63 across the two warps (R13 bug: tid&63
  // collapsed both warps onto the same 32 values -> half the stash garbage).
  {
    const int w    = wid & 3;
    const int t64p = (tid & 31) + 32 * sub;
    #pragma unroll
    for (int i = 0; i < 6; i++){
      const int s  = i >> 1;                     // stage 0,0,1,1,2,2
      const int pp = 128 * w + 64 * (i & 1) + t64p;
      float4 t = tw4[s * 512 + pp];
      *(float4*)&sdata[TWF + s * TWS + 4 * pp + 4 * (pp >> 2)] = t;
    }
  }
  pair_bar(wid);     // stash slice ready for this warp pair

  float tw[48];

  // ================= PASS 1: stages 0-2 (stride 1,2,4), global -> smem ======
  // Twiddles from the padded stash: float offset TWF + s*TWS + 20o + 4q.
  {
    const float* tb = &sdata[TWF + 20 * o];
    #pragma unroll
    for (int s = 0; s < 3; s++){
      #pragma unroll
      for (int qq = 0; qq < 4; qq++){
        float4 t = *(const float4*)&tb[s * TWS + 4 * qq];
        tw[(s*4+qq)*4+0] = t.x; tw[(s*4+qq)*4+1] = t.y;
        tw[(s*4+qq)*4+2] = t.z; tw[(s*4+qq)*4+3] = t.w;
      }
    }
  }
  // ---- g = 0 (x already in registers) ----
  {
    const int quad = 2 * sub;
    u64 v01[8], v23[8];
    v01[0]=pk2(a0.x,a1.x); v01[1]=pk2(a0.y,a1.y); v01[2]=pk2(a0.z,a1.z); v01[3]=pk2(a0.w,a1.w);
    v01[4]=pk2(b0.x,b1.x); v01[5]=pk2(b0.y,b1.y); v01[6]=pk2(b0.z,b1.z); v01[7]=pk2(b0.w,b1.w);
    v23[0]=pk2(a2.x,a3.x); v23[1]=pk2(a2.y,a3.y); v23[2]=pk2(a2.z,a3.z); v23[3]=pk2(a2.w,a3.w);
    v23[4]=pk2(b2.x,b3.x); v23[5]=pk2(b2.y,b3.y); v23[6]=pk2(b2.z,b3.z); v23[7]=pk2(b2.w,b3.w);
    radix8q(v01, v23, tw);
    #pragma unroll
    for (int c = 0; c < 8; c++){
      ulonglong2 u; u.x = v01[c]; u.y = v23[c];
      *(ulonglong2*)&sdata[widx(8 * o + c, quad)] = u;
    }
  }
  // ---- g = 1 ----
  {
    const int quad = 2 * sub + 1;
    const float* base = base0 + 4 * 1024;
    float4 c0 = *(const float4*)(base        );
    float4 d0 = *(const float4*)(base +    4 );
    float4 c1 = *(const float4*)(base + 1024 );
    float4 d1 = *(const float4*)(base + 1028 );
    float4 c2 = *(const float4*)(base + 2048 );
    float4 d2 = *(const float4*)(base + 2052 );
    float4 c3 = *(const float4*)(base + 3072 );
    float4 d3 = *(const float4*)(base + 3076 );
    u64 v01[8], v23[8];
    v01[0]=pk2(c0.x,c1.x); v01[1]=pk2(c0.y,c1.y); v01[2]=pk2(c0.z,c1.z); v01[3]=pk2(c0.w,c1.w);
    v01[4]=pk2(d0.x,d1.x); v01[5]=pk2(d0.y,d1.y); v01[6]=pk2(d0.z,d1.z); v01[7]=pk2(d0.w,d1.w);
    v23[0]=pk2(c2.x,c3.x); v23[1]=pk2(c2.y,c3.y); v23[2]=pk2(c2.z,c3.z); v23[3]=pk2(c2.w,c3.w);
    v23[4]=pk2(d2.x,d3.x); v23[5]=pk2(d2.y,d3.y); v23[6]=pk2(d2.z,d3.z); v23[7]=pk2(d2.w,d3.w);
    radix8q(v01, v23, tw);
    #pragma unroll
    for (int c = 0; c < 8; c++){
      ulonglong2 u; u.x = v01[c]; u.y = v23[c];
      *(ulonglong2*)&sdata[widx(8 * o + c, quad)] = u;
    }
  }

  // Hoist P2 twiddle loads above the barrier (independent of the data tile).
  const int bb = o >> 3, j = o & 7;
  load_tw(tw4, 3, 32 * bb + j, 8, tw);

  // Data tile is half-private (quads 2sub, 2sub+1 <-> tids of this half).
  half_bar(sub);

  // ================= PASS 2: stages 3-5 (stride 8,16,32) ====================
  {
    #pragma unroll
    for (int g = 0; g < 2; g++){
      const int quad = 2 * sub + g;
      // Compute the 8 smem addresses ONCE; reuse for load and store batches.
      int adr0 = widx(64 * bb + 8 * 0 + j, quad);
      int adr1 = widx(64 * bb + 8 * 1 + j, quad);
      int adr2 = widx(64 * bb + 8 * 2 + j, quad);
      int adr3 = widx(64 * bb + 8 * 3 + j, quad);
      int adr4 = widx(64 * bb + 8 * 4 + j, quad);
      int adr5 = widx(64 * bb + 8 * 5 + j, quad);
      int adr6 = widx(64 * bb + 8 * 6 + j, quad);
      int adr7 = widx(64 * bb + 8 * 7 + j, quad);
      u64 v01[8], v23[8];
      {
        ulonglong2 u;
        u = *(ulonglong2*)&sdata[adr0]; v01[0]=u.x; v23[0]=u.y;
        u = *(ulonglong2*)&sdata[adr1]; v01[1]=u.x; v23[1]=u.y;
        u = *(ulonglong2*)&sdata[adr2]; v01[2]=u.x; v23[2]=u.y;
        u = *(ulonglong2*)&sdata[adr3]; v01[3]=u.x; v23[3]=u.y;
        u = *(ulonglong2*)&sdata[adr4]; v01[4]=u.x; v23[4]=u.y;
        u = *(ulonglong2*)&sdata[adr5]; v01[5]=u.x; v23[5]=u.y;
        u = *(ulonglong2*)&sdata[adr6]; v01[6]=u.x; v23[6]=u.y;
        u = *(ulonglong2*)&sdata[adr7]; v01[7]=u.x; v23[7]=u.y;
      }
      radix8q(v01, v23, tw);
      {
        ulonglong2 u;
        u.x=v01[0]; u.y=v23[0]; *(ulonglong2*)&sdata[adr0] = u;
        u.x=v01[1]; u.y=v23[1]; *(ulonglong2*)&sdata[adr1] = u;
        u.x=v01[2]; u.y=v23[2]; *(ulonglong2*)&sdata[adr2] = u;
        u.x=v01[3]; u.y=v23[3]; *(ulonglong2*)&sdata[adr3] = u;
        u.x=v01[4]; u.y=v23[4]; *(ulonglong2*)&sdata[adr4] = u;
        u.x=v01[5]; u.y=v23[5]; *(ulonglong2*)&sdata[adr5] = u;
        u.x=v01[6]; u.y=v23[6]; *(ulonglong2*)&sdata[adr6] = u;
        u.x=v01[7]; u.y=v23[7]; *(ulonglong2*)&sdata[adr7] = u;
      }
    }
  }

  // Hoist bias loads above the barrier (independent of the data tile).
  const int j2 = tid & 63;
  const int q  = tid >> 6;           // quad 0..3; q>>1 == sub for this thread
  float bs[16];
  #pragma unroll
  for (int m = 0; m < 16; m++) bs[m] = bias[j2 + 64 * m];

  half_bar(sub);

  // ====== PASS 3: stages 6-9 (stride 64,128,256,512) + bias -> global =======
  // Thread owns pos = j2 + 64m, m=0..15, for one quad (4 rows); quads 2sub
  // and 2sub+1 were produced by this half. All four stages in registers.
  {
    u64 v01[16], v23[16];
    #pragma unroll
    for (int m = 0; m < 16; m++){
      ulonglong2 u = *(ulonglong2*)&sdata[widx(j2 + 64 * m, q)];
      v01[m] = u.x; v23[m] = u.y;
    }
    // stage 6 (S=64): pairs (2r, 2r+1); tw idx = 64r + j2
    #pragma unroll
    for (int r = 0; r < 8; r++){
      float4 t = tw4[6 * 512 + 64 * r + j2];
      float tm[4] = {t.x, t.y, t.z, t.w};
      bflyq(v01[2*r], v23[2*r], v01[2*r+1], v23[2*r+1], tm);
    }
    // stage 7 (S=128): pairs (4r+h, 4r+h+2); tw idx = 128r + 64h + j2
    #pragma unroll
    for (int r = 0; r < 4; r++){
      #pragma unroll
      for (int h = 0; h < 2; h++){
        float4 t = tw4[7 * 512 + 128 * r + 64 * h + j2];
        float tm[4] = {t.x, t.y, t.z, t.w};
        const int m0 = 4 * r + h;
        bflyq(v01[m0], v23[m0], v01[m0+2], v23[m0+2], tm);
      }
    }
    // stage 8 (S=256): pairs (8r+h, 8r+h+4); tw idx = 256r + 64h + j2
    #pragma unroll
    for (int r = 0; r < 2; r++){
      #pragma unroll
      for (int h = 0; h < 4; h++){
        float4 t = tw4[8 * 512 + 256 * r + 64 * h + j2];
        float tm[4] = {t.x, t.y, t.z, t.w};
        const int m0 = 8 * r + h;
        bflyq(v01[m0], v23[m0], v01[m0+4], v23[m0+4], tm);
      }
    }
    // stage 9 (S=512): pairs (h, h+8); tw idx = 64h + j2
    #pragma unroll
    for (int h = 0; h < 8; h++){
      float4 t = tw4[9 * 512 + 64 * h + j2];
      float tm[4] = {t.x, t.y, t.z, t.w};
      bflyq(v01[h], v23[h], v01[h+8], v23[h+8], tm);
    }
    // bias + store (lanes j2 consecutive -> 128B-coalesced STG.32)
    const long long r0 = (long long)blockIdx.x * 16 + 4 * q;
    float* obase = out + r0 * 1024 + j2;
    #pragma unroll
    for (int m = 0; m < 16; m++){
      u64 b2 = pk2(bs[m], bs[m]);
      u64 ylo = add2(v01[m], b2);
      u64 yhi = add2(v23[m], b2);
      float f0, f1, f2, f3;
      upk2(ylo, f0, f1); upk2(yhi, f2, f3);
      float* op = obase + 64 * m;
      op[0]    = f0;
      op[1024] = f1;
      op[2048] = f2;
      op[3072] = f3;
    }
  }
}

extern "C" void kernel_launch(void* const* d_in, const int* in_sizes, int n_in,
                              void* d_out, int out_size)
{
  const float* x    = (const float*)d_in[0];   // (32768, 1024) f32
  const float* tw   = (const float*)d_in[1];   // (1, 10, 512, 2, 2) f32
  const float* bias = (const float*)d_in[2];   // (1024,) f32
  float* out = (float*)d_out;                  // (32768, 1024) f32

  const int batch = in_sizes[0] / 1024;
  const int smem_bytes = (16384 + 3 * 2560) * 4;   // 64KB data + 30KB tw stash

  cudaFuncSetAttribute(butterfly_kernel,
                       cudaFuncAttributeMaxDynamicSharedMemorySize, smem_bytes);
  butterfly_kernel<<<batch / 16, 256, smem_bytes>>>(x, tw, bias, out);
}

// round 16
// speedup vs baseline: 3.2337x; 1.0023x over previous
#include <cuda_runtime.h>

typedef unsigned long long u64;

__device__ __forceinline__ u64 pk2(float lo, float hi){
  u64 r; asm volatile("mov.b64 %0, {%1,%2};" : "=l"(r) : "f"(lo), "f"(hi)); return r;
}
__device__ __forceinline__ void upk2(u64 v, float& lo, float& hi){
  asm("mov.b64 {%0,%1}, %2;" : "=f"(lo), "=f"(hi) : "l"(v));
}
__device__ __forceinline__ u64 fma2(u64 a, u64 b, u64 c){
  u64 d; asm("fma.rn.f32x2 %0, %1, %2, %3;" : "=l"(d) : "l"(a), "l"(b), "l"(c)); return d;
}
__device__ __forceinline__ u64 mul2(u64 a, u64 b){
  u64 d; asm("mul.rn.f32x2 %0, %1, %2;" : "=l"(d) : "l"(a), "l"(b)); return d;
}
__device__ __forceinline__ u64 add2(u64 a, u64 b){
  u64 d; asm("add.rn.f32x2 %0, %1, %2;" : "=l"(d) : "l"(a), "l"(b)); return d;
}

// Half-CTA barrier: half h (0/1) syncs its own 128 threads (ids 1,2).
__device__ __forceinline__ void half_bar(int h){
  asm volatile("bar.sync %0, 128;" :: "r"(h + 1) : "memory");
}
// Pair-warp barrier: warps {w, w+4} (64 threads) sync on id 4+(w&3).
__device__ __forceinline__ void pair_bar(int wid){
  asm volatile("bar.sync %0, 64;" :: "r"(4 + (wid & 3)) : "memory");
}

// 16 rows per CTA stored as 4 quads of 4 rows; one 16B slot per (position, quad).
// slot = (quad ^ (p>>1) ^ (p>>3)) & 3. (R5 layout — address math stays uniform.)
__device__ __forceinline__ int widx(int pos, int quad){
  return (pos << 4) + (((quad ^ (pos >> 1) ^ (pos >> 3)) & 3) << 2);
}

// Butterfly on one pair of positions for 4 rows (2 packed f32x2 lanes each).
__device__ __forceinline__ void bflyq(u64& x0a, u64& x0b, u64& x1a, u64& x1b,
                                      const float* t){
  u64 m0 = pk2(t[0], t[0]);
  u64 m1 = pk2(t[1], t[1]);
  u64 m2 = pk2(t[2], t[2]);
  u64 m3 = pk2(t[3], t[3]);
  u64 a = x0a, b = x1a;
  x0a = fma2(m0, a, mul2(m1, b));
  x1a = fma2(m2, a, mul2(m3, b));
  a = x0b; b = x1b;
  x0b = fma2(m0, a, mul2(m1, b));
  x1b = fma2(m2, a, mul2(m3, b));
}

// 3 stages on 8 local elements (local strides 1,2,4).
__device__ __forceinline__ void radix8q(u64 v01[8], u64 v23[8], const float tw[48]){
  bflyq(v01[0],v23[0], v01[1],v23[1], tw+ 0);
  bflyq(v01[2],v23[2], v01[3],v23[3], tw+ 4);
  bflyq(v01[4],v23[4], v01[5],v23[5], tw+ 8);
  bflyq(v01[6],v23[6], v01[7],v23[7], tw+12);
  bflyq(v01[0],v23[0], v01[2],v23[2], tw+16);
  bflyq(v01[1],v23[1], v01[3],v23[3], tw+20);
  bflyq(v01[4],v23[4], v01[6],v23[6], tw+24);
  bflyq(v01[5],v23[5], v01[7],v23[7], tw+28);
  bflyq(v01[0],v23[0], v01[4],v23[4], tw+32);
  bflyq(v01[1],v23[1], v01[5],v23[5], tw+36);
  bflyq(v01[2],v23[2], v01[6],v23[6], tw+40);
  bflyq(v01[3],v23[3], v01[7],v23[7], tw+44);
}

__device__ __forceinline__ void load_tw(const float4* __restrict__ tw4,
                                        int s0, int pbase, int pstride, float tw[48]){
  #pragma unroll
  for (int s = 0; s < 3; s++){
    #pragma unroll
    for (int i = 0; i < 4; i++){
      float4 t = tw4[(s0 + s) * 512 + pbase + i * pstride];
      tw[(s*4+i)*4+0] = t.x; tw[(s*4+i)*4+1] = t.y;
      tw[(s*4+i)*4+2] = t.z; tw[(s*4+i)*4+3] = t.w;
    }
  }
}

// Data tile: 16384 floats (64KB).
// Padded stage0-2 twiddle stash: float4 p of stage s lives at float offset
// TWF + s*2560 + 4p + 4*(p>>2) (consumer reads at 20o + immediates,
// conflict-free LDS.128).
#define TWF 16384
#define TWS 2560

__global__ __launch_bounds__(256, 2)
void butterfly_kernel(const float* __restrict__ x,
                      const float* __restrict__ twg,
                      const float* __restrict__ bias,
                      float* __restrict__ out)
{
  extern __shared__ float sdata[];   // 64KB data tile + 30KB padded tw stash
  const float4* tw4 = (const float4*)twg;
  const int tid = threadIdx.x;
  const int wid = tid >> 5;
  const int o   = tid & 127;         // position-octet index (P1/P2)
  const int sub = tid >> 7;          // row-half: 0 -> rows 0-7, 1 -> rows 8-15
  const long long rowbase = (long long)blockIdx.x * 16 + sub * 8;

  // ---- Hoist g=0 x-loads above the stash fill + barrier (hide DRAM lat) ----
  const float* base0 = x + rowbase * 1024 + 8 * o;
  float4 a0 = *(const float4*)(base0        );
  float4 b0 = *(const float4*)(base0 +    4 );
  float4 a1 = *(const float4*)(base0 + 1024 );
  float4 b1 = *(const float4*)(base0 + 1028 );
  float4 a2 = *(const float4*)(base0 + 2048 );
  float4 b2 = *(const float4*)(base0 + 2052 );
  float4 a3 = *(const float4*)(base0 + 3072 );
  float4 b3 = *(const float4*)(base0 + 3076 );

  // ---- Stage stage-0..2 twiddles into the padded stash, PAIR-WARP style ----
  // Warp pair {w, w+4} (w = wid&3) fills the slice its o-range [32w..32w+31]
  // consumes: stage s float4 indices [128w..128w+127]. Intra-pair index
  // t64p = lane + 32*sub spans 0..63 across the two warps.
  {
    const int w    = wid & 3;
    const int t64p = (tid & 31) + 32 * sub;
    #pragma unroll
    for (int i = 0; i < 6; i++){
      const int s  = i >> 1;                     // stage 0,0,1,1,2,2
      const int pp = 128 * w + 64 * (i & 1) + t64p;
      float4 t = tw4[s * 512 + pp];
      *(float4*)&sdata[TWF + s * TWS + 4 * pp + 4 * (pp >> 2)] = t;
    }
  }
  pair_bar(wid);     // stash slice ready for this warp pair

  float tw[48];

  // ================= PASS 1: stages 0-2 (stride 1,2,4), global -> smem ======
  // Twiddles from the padded stash: float offset TWF + s*TWS + 20o + 4q.
  {
    const float* tb = &sdata[TWF + 20 * o];
    #pragma unroll
    for (int s = 0; s < 3; s++){
      #pragma unroll
      for (int qq = 0; qq < 4; qq++){
        float4 t = *(const float4*)&tb[s * TWS + 4 * qq];
        tw[(s*4+qq)*4+0] = t.x; tw[(s*4+qq)*4+1] = t.y;
        tw[(s*4+qq)*4+2] = t.z; tw[(s*4+qq)*4+3] = t.w;
      }
    }
  }
  // ---- g = 0 (x already in registers) ----
  {
    const int quad = 2 * sub;
    u64 v01[8], v23[8];
    v01[0]=pk2(a0.x,a1.x); v01[1]=pk2(a0.y,a1.y); v01[2]=pk2(a0.z,a1.z); v01[3]=pk2(a0.w,a1.w);
    v01[4]=pk2(b0.x,b1.x); v01[5]=pk2(b0.y,b1.y); v01[6]=pk2(b0.z,b1.z); v01[7]=pk2(b0.w,b1.w);
    v23[0]=pk2(a2.x,a3.x); v23[1]=pk2(a2.y,a3.y); v23[2]=pk2(a2.z,a3.z); v23[3]=pk2(a2.w,a3.w);
    v23[4]=pk2(b2.x,b3.x); v23[5]=pk2(b2.y,b3.y); v23[6]=pk2(b2.z,b3.z); v23[7]=pk2(b2.w,b3.w);
    radix8q(v01, v23, tw);
    #pragma unroll
    for (int c = 0; c < 8; c++){
      ulonglong2 u; u.x = v01[c]; u.y = v23[c];
      *(ulonglong2*)&sdata[widx(8 * o + c, quad)] = u;
    }
  }
  // ---- g = 1 ----
  {
    const int quad = 2 * sub + 1;
    const float* base = base0 + 4 * 1024;
    float4 c0 = *(const float4*)(base        );
    float4 d0 = *(const float4*)(base +    4 );
    float4 c1 = *(const float4*)(base + 1024 );
    float4 d1 = *(const float4*)(base + 1028 );
    float4 c2 = *(const float4*)(base + 2048 );
    float4 d2 = *(const float4*)(base + 2052 );
    float4 c3 = *(const float4*)(base + 3072 );
    float4 d3 = *(const float4*)(base + 3076 );
    u64 v01[8], v23[8];
    v01[0]=pk2(c0.x,c1.x); v01[1]=pk2(c0.y,c1.y); v01[2]=pk2(c0.z,c1.z); v01[3]=pk2(c0.w,c1.w);
    v01[4]=pk2(d0.x,d1.x); v01[5]=pk2(d0.y,d1.y); v01[6]=pk2(d0.z,d1.z); v01[7]=pk2(d0.w,d1.w);
    v23[0]=pk2(c2.x,c3.x); v23[1]=pk2(c2.y,c3.y); v23[2]=pk2(c2.z,c3.z); v23[3]=pk2(c2.w,c3.w);
    v23[4]=pk2(d2.x,d3.x); v23[5]=pk2(d2.y,d3.y); v23[6]=pk2(d2.z,d3.z); v23[7]=pk2(d2.w,d3.w);
    radix8q(v01, v23, tw);
    #pragma unroll
    for (int c = 0; c < 8; c++){
      ulonglong2 u; u.x = v01[c]; u.y = v23[c];
      *(ulonglong2*)&sdata[widx(8 * o + c, quad)] = u;
    }
  }

  // Hoist P2 twiddle loads above the barrier (independent of the data tile).
  const int bb = o >> 3, j = o & 7;
  load_tw(tw4, 3, 32 * bb + j, 8, tw);

  // Data tile is half-private (quads 2sub, 2sub+1 <-> tids of this half).
  half_bar(sub);

  // ================= PASS 2: stages 3-5 (stride 8,16,32) ====================
  {
    #pragma unroll
    for (int g = 0; g < 2; g++){
      const int quad = 2 * sub + g;
      // Compute the 8 smem addresses ONCE; reuse for load and store batches.
      int adr0 = widx(64 * bb + 8 * 0 + j, quad);
      int adr1 = widx(64 * bb + 8 * 1 + j, quad);
      int adr2 = widx(64 * bb + 8 * 2 + j, quad);
      int adr3 = widx(64 * bb + 8 * 3 + j, quad);
      int adr4 = widx(64 * bb + 8 * 4 + j, quad);
      int adr5 = widx(64 * bb + 8 * 5 + j, quad);
      int adr6 = widx(64 * bb + 8 * 6 + j, quad);
      int adr7 = widx(64 * bb + 8 * 7 + j, quad);
      u64 v01[8], v23[8];
      {
        ulonglong2 u;
        u = *(ulonglong2*)&sdata[adr0]; v01[0]=u.x; v23[0]=u.y;
        u = *(ulonglong2*)&sdata[adr1]; v01[1]=u.x; v23[1]=u.y;
        u = *(ulonglong2*)&sdata[adr2]; v01[2]=u.x; v23[2]=u.y;
        u = *(ulonglong2*)&sdata[adr3]; v01[3]=u.x; v23[3]=u.y;
        u = *(ulonglong2*)&sdata[adr4]; v01[4]=u.x; v23[4]=u.y;
        u = *(ulonglong2*)&sdata[adr5]; v01[5]=u.x; v23[5]=u.y;
        u = *(ulonglong2*)&sdata[adr6]; v01[6]=u.x; v23[6]=u.y;
        u = *(ulonglong2*)&sdata[adr7]; v01[7]=u.x; v23[7]=u.y;
      }
      radix8q(v01, v23, tw);
      {
        ulonglong2 u;
        u.x=v01[0]; u.y=v23[0]; *(ulonglong2*)&sdata[adr0] = u;
        u.x=v01[1]; u.y=v23[1]; *(ulonglong2*)&sdata[adr1] = u;
        u.x=v01[2]; u.y=v23[2]; *(ulonglong2*)&sdata[adr2] = u;
        u.x=v01[3]; u.y=v23[3]; *(ulonglong2*)&sdata[adr3] = u;
        u.x=v01[4]; u.y=v23[4]; *(ulonglong2*)&sdata[adr4] = u;
        u.x=v01[5]; u.y=v23[5]; *(ulonglong2*)&sdata[adr5] = u;
        u.x=v01[6]; u.y=v23[6]; *(ulonglong2*)&sdata[adr6] = u;
        u.x=v01[7]; u.y=v23[7]; *(ulonglong2*)&sdata[adr7] = u;
      }
    }
  }

  // ---- Prefetch stage-6 twiddles ABOVE the barrier (independent of tile);
  //      their L2 latency drains during barrier + the P3 LDS burst. Bias
  //      loads move back into the store loop to pay the register bill.
  const int j2 = tid & 63;
  const int q  = tid >> 6;           // quad 0..3; q>>1 == sub for this thread
  float4 t6[8];
  #pragma unroll
  for (int r = 0; r < 8; r++) t6[r] = tw4[6 * 512 + 64 * r + j2];

  half_bar(sub);

  // ====== PASS 3: stages 6-9 (stride 64,128,256,512) + bias -> global =======
  // Thread owns pos = j2 + 64m, m=0..15, for one quad (4 rows); quads 2sub
  // and 2sub+1 were produced by this half. All four stages in registers.
  {
    u64 v01[16], v23[16];
    #pragma unroll
    for (int m = 0; m < 16; m++){
      ulonglong2 u = *(ulonglong2*)&sdata[widx(j2 + 64 * m, q)];
      v01[m] = u.x; v23[m] = u.y;
    }
    // stage 6 (S=64): pairs (2r, 2r+1); twiddles prefetched in t6[]
    #pragma unroll
    for (int r = 0; r < 8; r++){
      float tm[4] = {t6[r].x, t6[r].y, t6[r].z, t6[r].w};
      bflyq(v01[2*r], v23[2*r], v01[2*r+1], v23[2*r+1], tm);
    }
    // stage 7 (S=128): pairs (4r+h, 4r+h+2); tw idx = 128r + 64h + j2
    #pragma unroll
    for (int r = 0; r < 4; r++){
      #pragma unroll
      for (int h = 0; h < 2; h++){
        float4 t = tw4[7 * 512 + 128 * r + 64 * h + j2];
        float tm[4] = {t.x, t.y, t.z, t.w};
        const int m0 = 4 * r + h;
        bflyq(v01[m0], v23[m0], v01[m0+2], v23[m0+2], tm);
      }
    }
    // stage 8 (S=256): pairs (8r+h, 8r+h+4); tw idx = 256r + 64h + j2
    #pragma unroll
    for (int r = 0; r < 2; r++){
      #pragma unroll
      for (int h = 0; h < 4; h++){
        float4 t = tw4[8 * 512 + 256 * r + 64 * h + j2];
        float tm[4] = {t.x, t.y, t.z, t.w};
        const int m0 = 8 * r + h;
        bflyq(v01[m0], v23[m0], v01[m0+4], v23[m0+4], tm);
      }
    }
    // stage 9 (S=512): pairs (h, h+8); tw idx = 64h + j2
    #pragma unroll
    for (int h = 0; h < 8; h++){
      float4 t = tw4[9 * 512 + 64 * h + j2];
      float tm[4] = {t.x, t.y, t.z, t.w};
      bflyq(v01[h], v23[h], v01[h+8], v23[h+8], tm);
    }
    // bias (L1-hit by now) + store (lanes j2 consecutive -> coalesced STG.32)
    const long long r0 = (long long)blockIdx.x * 16 + 4 * q;
    float* obase = out + r0 * 1024 + j2;
    #pragma unroll
    for (int m = 0; m < 16; m++){
      float b = bias[j2 + 64 * m];
      u64 b2 = pk2(b, b);
      u64 ylo = add2(v01[m], b2);
      u64 yhi = add2(v23[m], b2);
      float f0, f1, f2, f3;
      upk2(ylo, f0, f1); upk2(yhi, f2, f3);
      float* op = obase + 64 * m;
      op[0]    = f0;
      op[1024] = f1;
      op[2048] = f2;
      op[3072] = f3;
    }
  }
}

extern "C" void kernel_launch(void* const* d_in, const int* in_sizes, int n_in,
                              void* d_out, int out_size)
{
  const float* x    = (const float*)d_in[0];   // (32768, 1024) f32
  const float* tw   = (const float*)d_in[1];   // (1, 10, 512, 2, 2) f32
  const float* bias = (const float*)d_in[2];   // (1024,) f32
  float* out = (float*)d_out;                  // (32768, 1024) f32

  const int batch = in_sizes[0] / 1024;
  const int smem_bytes = (16384 + 3 * 2560) * 4;   // 64KB data + 30KB tw stash

  cudaFuncSetAttribute(butterfly_kernel,
                       cudaFuncAttributeMaxDynamicSharedMemorySize, smem_bytes);
  butterfly_kernel<<<batch / 16, 256, smem_bytes>>>(x, tw, bias, out);
}

// round 17
// speedup vs baseline: 3.2942x; 1.0187x over previous
#include <cuda_runtime.h>

typedef unsigned long long u64;

__device__ __forceinline__ u64 pk2(float lo, float hi){
  u64 r; asm volatile("mov.b64 %0, {%1,%2};" : "=l"(r) : "f"(lo), "f"(hi)); return r;
}
__device__ __forceinline__ void upk2(u64 v, float& lo, float& hi){
  asm("mov.b64 {%0,%1}, %2;" : "=f"(lo), "=f"(hi) : "l"(v));
}
__device__ __forceinline__ u64 fma2(u64 a, u64 b, u64 c){
  u64 d; asm("fma.rn.f32x2 %0, %1, %2, %3;" : "=l"(d) : "l"(a), "l"(b), "l"(c)); return d;
}
__device__ __forceinline__ u64 mul2(u64 a, u64 b){
  u64 d; asm("mul.rn.f32x2 %0, %1, %2;" : "=l"(d) : "l"(a), "l"(b)); return d;
}
__device__ __forceinline__ u64 add2(u64 a, u64 b){
  u64 d; asm("add.rn.f32x2 %0, %1, %2;" : "=l"(d) : "l"(a), "l"(b)); return d;
}

// Half-CTA barrier: half h (0/1) syncs its own 128 threads (ids 1,2).
__device__ __forceinline__ void half_bar(int h){
  asm volatile("bar.sync %0, 128;" :: "r"(h + 1) : "memory");
}
// Pair-warp barrier: warps {w, w+4} (64 threads) sync on id 4+(w&3).
__device__ __forceinline__ void pair_bar(int wid){
  asm volatile("bar.sync %0, 64;" :: "r"(4 + (wid & 3)) : "memory");
}

// 16 rows per CTA stored as 4 quads of 4 rows; one 16B slot per (position, quad).
// slot = (quad ^ (p>>1) ^ (p>>3)) & 3. (R5 layout — address math stays uniform.)
__device__ __forceinline__ int widx(int pos, int quad){
  return (pos << 4) + (((quad ^ (pos >> 1) ^ (pos >> 3)) & 3) << 2);
}

// Butterfly on one pair of positions for 4 rows (2 packed f32x2 lanes each).
__device__ __forceinline__ void bflyq(u64& x0a, u64& x0b, u64& x1a, u64& x1b,
                                      const float* t){
  u64 m0 = pk2(t[0], t[0]);
  u64 m1 = pk2(t[1], t[1]);
  u64 m2 = pk2(t[2], t[2]);
  u64 m3 = pk2(t[3], t[3]);
  u64 a = x0a, b = x1a;
  x0a = fma2(m0, a, mul2(m1, b));
  x1a = fma2(m2, a, mul2(m3, b));
  a = x0b; b = x1b;
  x0b = fma2(m0, a, mul2(m1, b));
  x1b = fma2(m2, a, mul2(m3, b));
}

// 3 stages on 8 local elements (local strides 1,2,4).
__device__ __forceinline__ void radix8q(u64 v01[8], u64 v23[8], const float tw[48]){
  bflyq(v01[0],v23[0], v01[1],v23[1], tw+ 0);
  bflyq(v01[2],v23[2], v01[3],v23[3], tw+ 4);
  bflyq(v01[4],v23[4], v01[5],v23[5], tw+ 8);
  bflyq(v01[6],v23[6], v01[7],v23[7], tw+12);
  bflyq(v01[0],v23[0], v01[2],v23[2], tw+16);
  bflyq(v01[1],v23[1], v01[3],v23[3], tw+20);
  bflyq(v01[4],v23[4], v01[6],v23[6], tw+24);
  bflyq(v01[5],v23[5], v01[7],v23[7], tw+28);
  bflyq(v01[0],v23[0], v01[4],v23[4], tw+32);
  bflyq(v01[1],v23[1], v01[5],v23[5], tw+36);
  bflyq(v01[2],v23[2], v01[6],v23[6], tw+40);
  bflyq(v01[3],v23[3], v01[7],v23[7], tw+44);
}

__device__ __forceinline__ void load_tw(const float4* __restrict__ tw4,
                                        int s0, int pbase, int pstride, float tw[48]){
  #pragma unroll
  for (int s = 0; s < 3; s++){
    #pragma unroll
    for (int i = 0; i < 4; i++){
      float4 t = tw4[(s0 + s) * 512 + pbase + i * pstride];
      tw[(s*4+i)*4+0] = t.x; tw[(s*4+i)*4+1] = t.y;
      tw[(s*4+i)*4+2] = t.z; tw[(s*4+i)*4+3] = t.w;
    }
  }
}

// Data tile: 16384 floats (64KB).
// Padded stage0-2 twiddle stash: float4 p of stage s lives at float offset
// TWF + s*2560 + 4p + 4*(p>>2) (consumer reads at 20o + immediates,
// conflict-free LDS.128).
#define TWF 16384
#define TWS 2560

__global__ __launch_bounds__(256, 2)
void butterfly_kernel(const float* __restrict__ x,
                      const float* __restrict__ twg,
                      const float* __restrict__ bias,
                      float* __restrict__ out)
{
  extern __shared__ float sdata[];   // 64KB data tile + 30KB padded tw stash
  const float4* tw4 = (const float4*)twg;
  const int tid = threadIdx.x;
  const int wid = tid >> 5;
  const int o   = tid & 127;         // position-octet index (P1/P2)
  const int sub = tid >> 7;          // row-half: 0 -> rows 0-7, 1 -> rows 8-15
  const long long rowbase = (long long)blockIdx.x * 16 + sub * 8;

  // ---- Hoist g=0 x-loads above the stash fill + barrier (hide DRAM lat).
  //      __ldcs: x is a read-once stream -> evict-first, keep L2 for twiddles.
  const float* base0 = x + rowbase * 1024 + 8 * o;
  float4 a0 = __ldcs((const float4*)(base0        ));
  float4 b0 = __ldcs((const float4*)(base0 +    4 ));
  float4 a1 = __ldcs((const float4*)(base0 + 1024 ));
  float4 b1 = __ldcs((const float4*)(base0 + 1028 ));
  float4 a2 = __ldcs((const float4*)(base0 + 2048 ));
  float4 b2 = __ldcs((const float4*)(base0 + 2052 ));
  float4 a3 = __ldcs((const float4*)(base0 + 3072 ));
  float4 b3 = __ldcs((const float4*)(base0 + 3076 ));

  // ---- Stage stage-0..2 twiddles into the padded stash, PAIR-WARP style ----
  // Warp pair {w, w+4} (w = wid&3) fills the slice its o-range [32w..32w+31]
  // consumes: stage s float4 indices [128w..128w+127]. Intra-pair index
  // t64p = lane + 32*sub spans 0..63 across the two warps.
  {
    const int w    = wid & 3;
    const int t64p = (tid & 31) + 32 * sub;
    #pragma unroll
    for (int i = 0; i < 6; i++){
      const int s  = i >> 1;                     // stage 0,0,1,1,2,2
      const int pp = 128 * w + 64 * (i & 1) + t64p;
      float4 t = tw4[s * 512 + pp];
      *(float4*)&sdata[TWF + s * TWS + 4 * pp + 4 * (pp >> 2)] = t;
    }
  }
  pair_bar(wid);     // stash slice ready for this warp pair

  float tw[48];

  // ================= PASS 1: stages 0-2 (stride 1,2,4), global -> smem ======
  // Twiddles from the padded stash: float offset TWF + s*TWS + 20o + 4q.
  {
    const float* tb = &sdata[TWF + 20 * o];
    #pragma unroll
    for (int s = 0; s < 3; s++){
      #pragma unroll
      for (int qq = 0; qq < 4; qq++){
        float4 t = *(const float4*)&tb[s * TWS + 4 * qq];
        tw[(s*4+qq)*4+0] = t.x; tw[(s*4+qq)*4+1] = t.y;
        tw[(s*4+qq)*4+2] = t.z; tw[(s*4+qq)*4+3] = t.w;
      }
    }
  }
  // ---- g = 0 (x already in registers) ----
  {
    const int quad = 2 * sub;
    u64 v01[8], v23[8];
    v01[0]=pk2(a0.x,a1.x); v01[1]=pk2(a0.y,a1.y); v01[2]=pk2(a0.z,a1.z); v01[3]=pk2(a0.w,a1.w);
    v01[4]=pk2(b0.x,b1.x); v01[5]=pk2(b0.y,b1.y); v01[6]=pk2(b0.z,b1.z); v01[7]=pk2(b0.w,b1.w);
    v23[0]=pk2(a2.x,a3.x); v23[1]=pk2(a2.y,a3.y); v23[2]=pk2(a2.z,a3.z); v23[3]=pk2(a2.w,a3.w);
    v23[4]=pk2(b2.x,b3.x); v23[5]=pk2(b2.y,b3.y); v23[6]=pk2(b2.z,b3.z); v23[7]=pk2(b2.w,b3.w);
    radix8q(v01, v23, tw);
    #pragma unroll
    for (int c = 0; c < 8; c++){
      ulonglong2 u; u.x = v01[c]; u.y = v23[c];
      *(ulonglong2*)&sdata[widx(8 * o + c, quad)] = u;
    }
  }
  // ---- g = 1 ----
  {
    const int quad = 2 * sub + 1;
    const float* base = base0 + 4 * 1024;
    float4 c0 = __ldcs((const float4*)(base        ));
    float4 d0 = __ldcs((const float4*)(base +    4 ));
    float4 c1 = __ldcs((const float4*)(base + 1024 ));
    float4 d1 = __ldcs((const float4*)(base + 1028 ));
    float4 c2 = __ldcs((const float4*)(base + 2048 ));
    float4 d2 = __ldcs((const float4*)(base + 2052 ));
    float4 c3 = __ldcs((const float4*)(base + 3072 ));
    float4 d3 = __ldcs((const float4*)(base + 3076 ));
    u64 v01[8], v23[8];
    v01[0]=pk2(c0.x,c1.x); v01[1]=pk2(c0.y,c1.y); v01[2]=pk2(c0.z,c1.z); v01[3]=pk2(c0.w,c1.w);
    v01[4]=pk2(d0.x,d1.x); v01[5]=pk2(d0.y,d1.y); v01[6]=pk2(d0.z,d1.z); v01[7]=pk2(d0.w,d1.w);
    v23[0]=pk2(c2.x,c3.x); v23[1]=pk2(c2.y,c3.y); v23[2]=pk2(c2.z,c3.z); v23[3]=pk2(c2.w,c3.w);
    v23[4]=pk2(d2.x,d3.x); v23[5]=pk2(d2.y,d3.y); v23[6]=pk2(d2.z,d3.z); v23[7]=pk2(d2.w,d3.w);
    radix8q(v01, v23, tw);
    #pragma unroll
    for (int c = 0; c < 8; c++){
      ulonglong2 u; u.x = v01[c]; u.y = v23[c];
      *(ulonglong2*)&sdata[widx(8 * o + c, quad)] = u;
    }
  }

  // Hoist P2 twiddle loads above the barrier (independent of the data tile).
  const int bb = o >> 3, j = o & 7;
  load_tw(tw4, 3, 32 * bb + j, 8, tw);

  // Data tile is half-private (quads 2sub, 2sub+1 <-> tids of this half).
  half_bar(sub);

  // ================= PASS 2: stages 3-5 (stride 8,16,32) ====================
  {
    #pragma unroll
    for (int g = 0; g < 2; g++){
      const int quad = 2 * sub + g;
      // Compute the 8 smem addresses ONCE; reuse for load and store batches.
      int adr0 = widx(64 * bb + 8 * 0 + j, quad);
      int adr1 = widx(64 * bb + 8 * 1 + j, quad);
      int adr2 = widx(64 * bb + 8 * 2 + j, quad);
      int adr3 = widx(64 * bb + 8 * 3 + j, quad);
      int adr4 = widx(64 * bb + 8 * 4 + j, quad);
      int adr5 = widx(64 * bb + 8 * 5 + j, quad);
      int adr6 = widx(64 * bb + 8 * 6 + j, quad);
      int adr7 = widx(64 * bb + 8 * 7 + j, quad);
      u64 v01[8], v23[8];
      {
        ulonglong2 u;
        u = *(ulonglong2*)&sdata[adr0]; v01[0]=u.x; v23[0]=u.y;
        u = *(ulonglong2*)&sdata[adr1]; v01[1]=u.x; v23[1]=u.y;
        u = *(ulonglong2*)&sdata[adr2]; v01[2]=u.x; v23[2]=u.y;
        u = *(ulonglong2*)&sdata[adr3]; v01[3]=u.x; v23[3]=u.y;
        u = *(ulonglong2*)&sdata[adr4]; v01[4]=u.x; v23[4]=u.y;
        u = *(ulonglong2*)&sdata[adr5]; v01[5]=u.x; v23[5]=u.y;
        u = *(ulonglong2*)&sdata[adr6]; v01[6]=u.x; v23[6]=u.y;
        u = *(ulonglong2*)&sdata[adr7]; v01[7]=u.x; v23[7]=u.y;
      }
      radix8q(v01, v23, tw);
      {
        ulonglong2 u;
        u.x=v01[0]; u.y=v23[0]; *(ulonglong2*)&sdata[adr0] = u;
        u.x=v01[1]; u.y=v23[1]; *(ulonglong2*)&sdata[adr1] = u;
        u.x=v01[2]; u.y=v23[2]; *(ulonglong2*)&sdata[adr2] = u;
        u.x=v01[3]; u.y=v23[3]; *(ulonglong2*)&sdata[adr3] = u;
        u.x=v01[4]; u.y=v23[4]; *(ulonglong2*)&sdata[adr4] = u;
        u.x=v01[5]; u.y=v23[5]; *(ulonglong2*)&sdata[adr5] = u;
        u.x=v01[6]; u.y=v23[6]; *(ulonglong2*)&sdata[adr6] = u;
        u.x=v01[7]; u.y=v23[7]; *(ulonglong2*)&sdata[adr7] = u;
      }
    }
  }

  // ---- Prefetch stage-6 twiddles ABOVE the barrier (independent of tile);
  //      their L2 latency drains during barrier + the P3 LDS burst.
  const int j2 = tid & 63;
  const int q  = tid >> 6;           // quad 0..3; q>>1 == sub for this thread
  float4 t6[8];
  #pragma unroll
  for (int r = 0; r < 8; r++) t6[r] = tw4[6 * 512 + 64 * r + j2];

  half_bar(sub);

  // ====== PASS 3: stages 6-9 (stride 64,128,256,512) + bias -> global =======
  // Thread owns pos = j2 + 64m, m=0..15, for one quad (4 rows); quads 2sub
  // and 2sub+1 were produced by this half. All four stages in registers.
  {
    u64 v01[16], v23[16];
    #pragma unroll
    for (int m = 0; m < 16; m++){
      ulonglong2 u = *(ulonglong2*)&sdata[widx(j2 + 64 * m, q)];
      v01[m] = u.x; v23[m] = u.y;
    }
    // stage 6 (S=64): pairs (2r, 2r+1); twiddles prefetched in t6[]
    #pragma unroll
    for (int r = 0; r < 8; r++){
      float tm[4] = {t6[r].x, t6[r].y, t6[r].z, t6[r].w};
      bflyq(v01[2*r], v23[2*r], v01[2*r+1], v23[2*r+1], tm);
    }
    // stage 7 (S=128): pairs (4r+h, 4r+h+2); tw idx = 128r + 64h + j2
    #pragma unroll
    for (int r = 0; r < 4; r++){
      #pragma unroll
      for (int h = 0; h < 2; h++){
        float4 t = tw4[7 * 512 + 128 * r + 64 * h + j2];
        float tm[4] = {t.x, t.y, t.z, t.w};
        const int m0 = 4 * r + h;
        bflyq(v01[m0], v23[m0], v01[m0+2], v23[m0+2], tm);
      }
    }
    // stage 8 (S=256): pairs (8r+h, 8r+h+4); tw idx = 256r + 64h + j2
    #pragma unroll
    for (int r = 0; r < 2; r++){
      #pragma unroll
      for (int h = 0; h < 4; h++){
        float4 t = tw4[8 * 512 + 256 * r + 64 * h + j2];
        float tm[4] = {t.x, t.y, t.z, t.w};
        const int m0 = 8 * r + h;
        bflyq(v01[m0], v23[m0], v01[m0+4], v23[m0+4], tm);
      }
    }
    // stage 9 (S=512): pairs (h, h+8); tw idx = 64h + j2
    #pragma unroll
    for (int h = 0; h < 8; h++){
      float4 t = tw4[9 * 512 + 64 * h + j2];
      float tm[4] = {t.x, t.y, t.z, t.w};
      bflyq(v01[h], v23[h], v01[h+8], v23[h+8], tm);
    }
    // bias (L1-hit) + store; __stcs: out is a write-once stream.
    const long long r0 = (long long)blockIdx.x * 16 + 4 * q;
    float* obase = out + r0 * 1024 + j2;
    #pragma unroll
    for (int m = 0; m < 16; m++){
      float b = bias[j2 + 64 * m];
      u64 b2 = pk2(b, b);
      u64 ylo = add2(v01[m], b2);
      u64 yhi = add2(v23[m], b2);
      float f0, f1, f2, f3;
      upk2(ylo, f0, f1); upk2(yhi, f2, f3);
      float* op = obase + 64 * m;
      __stcs(op,        f0);
      __stcs(op + 1024, f1);
      __stcs(op + 2048, f2);
      __stcs(op + 3072, f3);
    }
  }
}

extern "C" void kernel_launch(void* const* d_in, const int* in_sizes, int n_in,
                              void* d_out, int out_size)
{
  const float* x    = (const float*)d_in[0];   // (32768, 1024) f32
  const float* tw   = (const float*)d_in[1];   // (1, 10, 512, 2, 2) f32
  const float* bias = (const float*)d_in[2];   // (1024,) f32
  float* out = (float*)d_out;                  // (32768, 1024) f32

  const int batch = in_sizes[0] / 1024;
  const int smem_bytes = (16384 + 3 * 2560) * 4;   // 64KB data + 30KB tw stash

  cudaFuncSetAttribute(butterfly_kernel,
                       cudaFuncAttributeMaxDynamicSharedMemorySize, smem_bytes);
  butterfly_kernel<<<batch / 16, 256, smem_bytes>>>(x, tw, bias, out);
}